// round 13
// baseline (speedup 1.0000x reference)
#include <cuda_runtime.h>
#include <math.h>

// Problem constants (fixed shapes per reference)
#define BB 4
#define NN 8192
#define KK 16
#define NPATCH 32
#define PP 256            // points per patch
#define NTILE 512         // 16-point tiles per batch
#define TSZ 16            // tile size
#define NSUPER 32         // 256-point super-tiles per batch
#define NCELL 4096        // 16^3 Morton cells
#define BCAP 32           // per-thread hit buffer capacity

// ---------------- scratch (no allocations allowed) ----------------
__device__ float4 g_sorted[BB * NN];       // spatially sorted points (+|c|^2 in .w)
__device__ int    g_perm[BB * NN];         // sorted slot -> original index
__device__ float  g_nrm_abs[BB * NN * 3];  // |global normal| (original index order)
__device__ float  g_sv[BB * NN];           // global surface variance
__device__ double g_pn[BB * NPATCH];       // per-patch partial normal loss
__device__ double g_psv[BB * NPATCH];      // per-patch partial surfvar loss
__device__ unsigned int g_done;            // patch-block arrival counter

// ---------------- sorted insertion into ascending top-16 ----------------
__device__ __forceinline__ void insert16(float v, int j, float (&ds)[KK], int (&is)[KK]) {
    bool pt = v < ds[KK - 1];
#pragma unroll
    for (int t = KK - 1; t >= 1; --t) {
        bool pm = v < ds[t - 1];
        float nv = pm ? ds[t - 1] : v;
        int   ni = pm ? is[t - 1] : j;
        ds[t] = pt ? nv : ds[t];
        is[t] = pt ? ni : is[t];
        pt = pm;
    }
    ds[0] = pt ? v : ds[0];
    is[0] = pt ? j : is[0];
}

// ---------------- analytic 3x3 symmetric eigensolver ----------------
__device__ __forceinline__ void eig3(float a00, float a01, float a02,
                                     float a11, float a12, float a22,
                                     float &l0, float &l1, float &l2,
                                     float &vx, float &vy, float &vz) {
    float q = (a00 + a11 + a22) * (1.0f / 3.0f);
    float b00 = a00 - q, b11 = a11 - q, b22 = a22 - q;
    float p1 = a01 * a01 + a02 * a02 + a12 * a12;
    float p2 = b00 * b00 + b11 * b11 + b22 * b22 + 2.0f * p1;
    if (p2 <= 1e-30f) {
        l0 = l1 = l2 = q;
        vx = 1.0f; vy = 0.0f; vz = 0.0f;
        return;
    }
    float p = sqrtf(p2 * (1.0f / 6.0f));
    float ip = 1.0f / p;
    float c00 = b00 * ip, c11 = b11 * ip, c22 = b22 * ip;
    float c01 = a01 * ip, c02 = a02 * ip, c12 = a12 * ip;
    float det = c00 * (c11 * c22 - c12 * c12)
              - c01 * (c01 * c22 - c12 * c02)
              + c02 * (c01 * c12 - c11 * c02);
    float r = 0.5f * det;
    r = fminf(1.0f, fmaxf(-1.0f, r));
    float phi = acosf(r) * (1.0f / 3.0f);
    float two_p = 2.0f * p;
    l2 = q + two_p * cosf(phi);                          // largest
    l0 = q + two_p * cosf(phi + 2.0943951023931953f);    // smallest
    l1 = 3.0f * q - l2 - l0;

    float m00 = a00 - l0, m11 = a11 - l0, m22 = a22 - l0;
    float x0 = a01 * a12 - a02 * m11;
    float y0 = a02 * a01 - m00 * a12;
    float z0 = m00 * m11 - a01 * a01;
    float x1 = a01 * m22 - a02 * a12;
    float y1 = a02 * a02 - m00 * m22;
    float z1 = m00 * a12 - a01 * a02;
    float x2 = m11 * m22 - a12 * a12;
    float y2 = a12 * a02 - a01 * m22;
    float z2 = a01 * a12 - m11 * a02;
    float n0 = x0 * x0 + y0 * y0 + z0 * z0;
    float n1 = x1 * x1 + y1 * y1 + z1 * z1;
    float n2 = x2 * x2 + y2 * y2 + z2 * z2;
    float bx = x0, by = y0, bz = z0, bn = n0;
    if (n1 > bn) { bx = x1; by = y1; bz = z1; bn = n1; }
    if (n2 > bn) { bx = x2; by = y2; bz = z2; bn = n2; }
    if (bn < 1e-40f) { bx = 1.0f; by = 0.0f; bz = 0.0f; bn = 1.0f; }
    float inv = rsqrtf(bn);
    vx = bx * inv; vy = by * inv; vz = bz * inv;
}

// ---------------- covariance of centered neighbor set + eig ----------------
__device__ __forceinline__ void cov_eig(const float4* __restrict__ sh,
                                        float qx, float qy, float qz,
                                        const int (&is)[KK],
                                        float &l0, float &l1, float &l2,
                                        float &vx, float &vy, float &vz) {
    float a00 = 0.f, a01 = 0.f, a02 = 0.f, a11 = 0.f, a12 = 0.f, a22 = 0.f;
#pragma unroll
    for (int t = 0; t < KK; ++t) {
        float4 nb = sh[is[t]];
        float dx = nb.x - qx, dy = nb.y - qy, dz = nb.z - qz;
        a00 = fmaf(dx, dx, a00); a01 = fmaf(dx, dy, a01); a02 = fmaf(dx, dz, a02);
        a11 = fmaf(dy, dy, a11); a12 = fmaf(dy, dz, a12); a22 = fmaf(dz, dz, a22);
    }
    eig3(a00, a01, a02, a11, a12, a22, l0, l1, l2, vx, vy, vz);
}

// ---------------- kernel 0: spatial counting sort (12-bit Morton, 16^3) ------
// Within-cell slot order comes from smem atomics (nondeterministic), which does
// not affect outputs: selection is exact and cov order is distance-sorted.
__device__ __forceinline__ unsigned int morton12(float x, float y, float z) {
    int ux = min(15, max(0, (int)((x + 4.0f) * 2.0f)));
    int uy = min(15, max(0, (int)((y + 4.0f) * 2.0f)));
    int uz = min(15, max(0, (int)((z + 4.0f) * 2.0f)));
    unsigned int code = 0;
#pragma unroll
    for (int b = 0; b < 4; ++b) {
        code |= ((ux >> b) & 1) << (3 * b + 0);
        code |= ((uy >> b) & 1) << (3 * b + 1);
        code |= ((uz >> b) & 1) << (3 * b + 2);
    }
    return code;
}

__global__ void __launch_bounds__(512)
sort_kernel(const float* __restrict__ pc) {
    __shared__ int hist[NCELL];
    __shared__ int part[512];
    __shared__ int offs[NCELL];
    __shared__ int cnt[NCELL];

    const int b = blockIdx.x;
    const float* base = pc + (size_t)b * NN * 3;
    const int t = threadIdx.x;

    if (b == 0 && t == 0) g_done = 0;   // reset arrival counter each replay

    for (int i = t; i < NCELL; i += 512) { hist[i] = 0; cnt[i] = 0; }
    __syncthreads();

    // pass 1: histogram
    for (int i = t; i < NN; i += 512) {
        float x = base[i * 3 + 0];
        float y = base[i * 3 + 1];
        float z = base[i * 3 + 2];
        atomicAdd(&hist[morton12(x, y, z)], 1);
    }
    __syncthreads();

    // block scan over 4096 bins: 8 bins/thread + Hillis-Steele over 512 partials
    int s = 0;
#pragma unroll
    for (int u = 0; u < 8; ++u) s += hist[t * 8 + u];
    part[t] = s;
    __syncthreads();
    for (int o = 1; o < 512; o <<= 1) {
        int v = (t >= o) ? part[t - o] : 0;
        __syncthreads();
        part[t] += v;
        __syncthreads();
    }
    {
        int basev = part[t] - s;
#pragma unroll
        for (int u = 0; u < 8; ++u) {
            offs[t * 8 + u] = basev;
            basev += hist[t * 8 + u];
        }
    }
    __syncthreads();

    // pass 2: scatter
    for (int i = t; i < NN; i += 512) {
        float x = base[i * 3 + 0];
        float y = base[i * 3 + 1];
        float z = base[i * 3 + 2];
        unsigned int c = morton12(x, y, z);
        int pos = offs[c] + atomicAdd(&cnt[c], 1);
        float c2 = __fadd_rn(__fadd_rn(__fmul_rn(x, x), __fmul_rn(y, y)), __fmul_rn(z, z));
        g_sorted[b * NN + pos] = make_float4(x, y, z, c2);
        g_perm[b * NN + pos] = i;
    }
}

// ---------------- kernel 1: global kNN, 2-level outward prune + seeded wmax --
// smem: float4 pts[8192] (128K) | float4 boxmin/boxmax[512] (16K)
//       | float4 sboxmin/sboxmax[32] (1K) | float mds[256*16] | int mis[256*16] (32K)
extern __shared__ unsigned char smem_raw[];

__global__ void __launch_bounds__(512, 1)
knn_global_kernel(const float* __restrict__ pc) {
    float4* sh      = (float4*)smem_raw;
    float4* boxmin  = (float4*)(smem_raw + NN * 16);
    float4* boxmax  = (float4*)(smem_raw + NN * 16 + NTILE * 16);
    float4* sboxmin = (float4*)(smem_raw + NN * 16 + 2 * NTILE * 16);
    float4* sboxmax = (float4*)(smem_raw + NN * 16 + 2 * NTILE * 16 + NSUPER * 16);
    float*  mds     = (float*)(smem_raw + NN * 16 + 2 * NTILE * 16 + 2 * NSUPER * 16);
    int*    mis     = (int*)(smem_raw + NN * 16 + 2 * NTILE * 16 + 2 * NSUPER * 16
                             + 256 * KK * 4);

    const int b = blockIdx.y;
    const float4* gs = g_sorted + b * NN;

    // stage sorted points
    for (int i = threadIdx.x; i < NN; i += 512) sh[i] = gs[i];
    __syncthreads();

    // tile AABBs (512 tiles, one per thread)
    {
        const int T = threadIdx.x;
        float4 p0 = sh[T * TSZ];
        float mnx = p0.x, mny = p0.y, mnz = p0.z;
        float mxx = p0.x, mxy = p0.y, mxz = p0.z;
#pragma unroll
        for (int u = 1; u < TSZ; ++u) {
            float4 p = sh[T * TSZ + u];
            mnx = fminf(mnx, p.x); mny = fminf(mny, p.y); mnz = fminf(mnz, p.z);
            mxx = fmaxf(mxx, p.x); mxy = fmaxf(mxy, p.y); mxz = fmaxf(mxz, p.z);
        }
        boxmin[T] = make_float4(mnx, mny, mnz, 0.f);
        boxmax[T] = make_float4(mxx, mxy, mxz, 0.f);
    }
    __syncthreads();

    // super-tile AABBs (32 supers, one per thread)
    if (threadIdx.x < NSUPER) {
        const int S = threadIdx.x;
        float4 m0 = boxmin[S * 16];
        float4 M0 = boxmax[S * 16];
        float mnx = m0.x, mny = m0.y, mnz = m0.z;
        float mxx = M0.x, mxy = M0.y, mxz = M0.z;
#pragma unroll
        for (int u = 1; u < 16; ++u) {
            float4 m = boxmin[S * 16 + u];
            float4 M = boxmax[S * 16 + u];
            mnx = fminf(mnx, m.x); mny = fminf(mny, m.y); mnz = fminf(mnz, m.z);
            mxx = fmaxf(mxx, M.x); mxy = fmaxf(mxy, M.y); mxz = fmaxf(mxz, M.z);
        }
        sboxmin[S] = make_float4(mnx, mny, mnz, 0.f);
        sboxmax[S] = make_float4(mxx, mxy, mxz, 0.f);
    }
    __syncthreads();

    const int q    = threadIdx.x & 255;       // query slot within block
    const int half = threadIdx.x >> 8;        // tile-parity this thread scans
    const int qi   = blockIdx.x * 256 + q;    // sorted index of query

    float4 qp = sh[qi];
    const float qx = qp.x, qy = qp.y, qz = qp.z, q2 = qp.w;
    const float nqx = -2.0f * qx, nqy = -2.0f * qy, nqz = -2.0f * qz;

    // --- seed: own tile has exactly 16 points -> max of their computed rank
    //     keys is a valid upper bound on the final 16th key. Ladder-free.
    float wmax = -3.4e38f;
    {
        const int jb0 = (qi >> 4) << 4;
#pragma unroll
        for (int u = 0; u < TSZ; ++u) {
            float4 c = sh[jb0 + u];
            float d = fmaf(c.x, nqx, fmaf(c.y, nqy, fmaf(c.z, nqz, c.w)));
            wmax = fmaxf(wmax, d);
        }
    }
    // prune threshold in true-d2 space, inflated for rank-key rounding slack
    float wmax_d2 = fmaf(fabsf(wmax + q2), 1e-4f, wmax + q2) + 1e-6f;

    float ds[KK];
    int   is[KK];
#pragma unroll
    for (int t = 0; t < KK; ++t) { ds[t] = 3.4e38f; is[t] = 0; }

    float bufd[BCAP];
    int   bufi[BCAP];
    int   cnt = 0;

    // outward loop over supers; this block's queries all live in super blockIdx.x
    int a = blockIdx.x, bd = blockIdx.x - 1;

    for (int s = 0; s < NSUPER; ++s) {
        int S;
        bool canA = (a < NSUPER), canB = (bd >= 0);
        if (canA && (!canB || ((s & 1) == 0))) { S = a; ++a; }
        else                                   { S = bd; --bd; }

        // super-level conservative AABB bound
        float4 smn = sboxmin[S];
        float4 smx = sboxmax[S];
        float sx = fmaxf(fmaxf(smn.x - qx, qx - smx.x), 0.f);
        float sy = fmaxf(fmaxf(smn.y - qy, qy - smx.y), 0.f);
        float sz = fmaxf(fmaxf(smn.z - qz, qz - smx.z), 0.f);
        float sd2 = fmaf(sx, sx, fmaf(sy, sy, sz * sz));
        if (!__any_sync(0xffffffffu, sd2 < wmax_d2)) continue;

        // descend: this parity's 8 tiles within super S
#pragma unroll
        for (int i = 0; i < 8; ++i) {
            const int T = (S << 4) | (i << 1) | half;
            float4 bmn = boxmin[T];
            float4 bmx = boxmax[T];
            float dx = fmaxf(fmaxf(bmn.x - qx, qx - bmx.x), 0.f);
            float dy = fmaxf(fmaxf(bmn.y - qy, qy - bmx.y), 0.f);
            float dz = fmaxf(fmaxf(bmn.z - qz, qz - bmx.z), 0.f);
            float d2b = fmaf(dx, dx, fmaf(dy, dy, dz * dz));

            if (__any_sync(0xffffffffu, d2b < wmax_d2)) {
                const int jb = T << 4;
#pragma unroll
                for (int u = 0; u < TSZ; ++u) {
                    float4 c = sh[jb + u];
                    float d = fmaf(c.x, nqx, fmaf(c.y, nqy, fmaf(c.z, nqz, c.w)));
                    if (d <= wmax) {        // <= keeps the seed-boundary point
                        bufd[cnt] = d;
                        bufi[cnt] = jb + u;
                        ++cnt;
                    }
                }
                if (__any_sync(0xffffffffu, cnt > BCAP - TSZ)) {
#pragma unroll
                    for (int t = 0; t < BCAP; ++t) {
                        if (t < cnt) insert16(bufd[t], bufi[t], ds, is);
                    }
                    cnt = 0;
                    wmax = fminf(wmax, ds[KK - 1]);
                    wmax_d2 = fmaf(fabsf(wmax + q2), 1e-4f, wmax + q2) + 1e-6f;
                }
            }
        }
    }
    // drain remaining buffered hits
#pragma unroll
    for (int t = 0; t < BCAP; ++t) {
        if (t < cnt) insert16(bufd[t], bufi[t], ds, is);
    }

    // merge the two parity halves
    if (half) {
#pragma unroll
        for (int t = 0; t < KK; ++t) {
            mds[q * KK + t] = ds[t];
            mis[q * KK + t] = is[t];
        }
    }
    __syncthreads();

    if (!half) {
#pragma unroll
        for (int t = 0; t < KK; ++t) {
            float v = mds[q * KK + t];
            if (v < ds[KK - 1]) insert16(v, mis[q * KK + t], ds, is);
        }

        float l0, l1, l2, vx, vy, vz;
        cov_eig(sh, qx, qy, qz, is, l0, l1, l2, vx, vy, vz);

        const int gi = b * NN + g_perm[b * NN + qi];   // original point index
        g_nrm_abs[gi * 3 + 0] = fabsf(vx);
        g_nrm_abs[gi * 3 + 1] = fabsf(vy);
        g_nrm_abs[gi * 3 + 2] = fabsf(vz);
        g_sv[gi] = l0 / (l0 + l1 + l2);
    }
}

// ---------------- kernel 2: patch kNN + eig + loss + folded final reduction ---
__global__ void __launch_bounds__(PP, 4)
knn_patch_kernel(const float* __restrict__ pc, float* __restrict__ out) {
    __shared__ float4 shp[PP];
    __shared__ double s_n[PP];
    __shared__ double s_sv[PP];
    __shared__ bool   s_last;

    const int patch = blockIdx.x;              // 0 .. BB*NPATCH-1
    const float* base = pc + (size_t)patch * PP * 3;
    const int t = threadIdx.x;

    {
        float x = base[t * 3 + 0];
        float y = base[t * 3 + 1];
        float z = base[t * 3 + 2];
        float c2 = __fadd_rn(__fadd_rn(__fmul_rn(x, x), __fmul_rn(y, y)), __fmul_rn(z, z));
        shp[t] = make_float4(x, y, z, c2);
    }
    __syncthreads();

    float4 qp = shp[t];
    const float nqx = -2.0f * qp.x, nqy = -2.0f * qp.y, nqz = -2.0f * qp.z;

    float ds[KK];
    int   is[KK];
#pragma unroll
    for (int k = 0; k < KK; ++k) { ds[k] = 3.4e38f; is[k] = 0; }

    {
        float bufd[BCAP];
        int   bufi[BCAP];
        int   cnt = 0;
        float wmax = 3.4e38f;
        for (int j = 0; j < PP; j += 8) {
            float d[8];
#pragma unroll
            for (int u = 0; u < 8; ++u) {
                float4 c = shp[j + u];
                d[u] = fmaf(c.x, nqx, fmaf(c.y, nqy, fmaf(c.z, nqz, c.w)));
            }
            float m = fminf(fminf(fminf(d[0], d[1]), fminf(d[2], d[3])),
                            fminf(fminf(d[4], d[5]), fminf(d[6], d[7])));
            if (m < wmax) {
#pragma unroll
                for (int u = 0; u < 8; ++u) {
                    if (d[u] < wmax) { bufd[cnt] = d[u]; bufi[cnt] = j + u; ++cnt; }
                }
            }
            if (__any_sync(0xffffffffu, cnt > BCAP - 8)) {
#pragma unroll
                for (int s = 0; s < BCAP; ++s) {
                    if (s < cnt) insert16(bufd[s], bufi[s], ds, is);
                }
                cnt = 0;
                wmax = ds[KK - 1];
            }
        }
#pragma unroll
        for (int s = 0; s < BCAP; ++s) {
            if (s < cnt) insert16(bufd[s], bufi[s], ds, is);
        }
    }

    float l0, l1, l2, vx, vy, vz;
    cov_eig(shp, qp.x, qp.y, qp.z, is, l0, l1, l2, vx, vy, vz);

    const int gi = patch * PP + t;   // == flat [B, N] original index
    float svp = l0 / (l0 + l1 + l2);

    float gx = g_nrm_abs[gi * 3 + 0];
    float gy = g_nrm_abs[gi * 3 + 1];
    float gz = g_nrm_abs[gi * 3 + 2];
    float ex = fabsf(vx) - gx;
    float ey = fabsf(vy) - gy;
    float ez = fabsf(vz) - gz;
    float ln = sqrtf(ex * ex + ey * ey + ez * ez);

    float dsv = svp - g_sv[gi];
    float lsv = dsv * dsv;

    // deterministic block reduction
    s_n[t]  = (double)ln;
    s_sv[t] = (double)lsv;
    __syncthreads();
#pragma unroll
    for (int s = PP / 2; s > 0; s >>= 1) {
        if (t < s) { s_n[t] += s_n[t + s]; s_sv[t] += s_sv[t + s]; }
        __syncthreads();
    }
    if (t == 0) {
        g_pn[patch]  = s_n[0];
        g_psv[patch] = s_sv[0];
        __threadfence();
        unsigned int v = atomicAdd(&g_done, 1);
        s_last = (v == BB * NPATCH - 1);
    }
    __syncthreads();

    // last-arriving block performs the deterministic final reduction
    if (s_last) {
        if (t < BB * NPATCH) {
            s_n[t]  = __ldcg(&g_pn[t]);     // bypass L1: other SMs wrote these
            s_sv[t] = __ldcg(&g_psv[t]);
        } else {
            s_n[t] = 0.0; s_sv[t] = 0.0;
        }
        __syncthreads();
#pragma unroll
        for (int s = PP / 2; s > 0; s >>= 1) {
            if (t < s) { s_n[t] += s_n[t + s]; s_sv[t] += s_sv[t + s]; }
            __syncthreads();
        }
        if (t == 0) {
            const double inv = 1.0 / (double)(BB * NN);
            out[0] = (float)(s_n[0]  * inv);   // * W_NORMAL (=1)
            out[1] = (float)(s_sv[0] * inv);   // * W_SURFVAR (=1)
        }
    }
}

// ---------------- launcher ----------------
extern "C" void kernel_launch(void* const* d_in, const int* in_sizes, int n_in,
                              void* d_out, int out_size) {
    (void)in_sizes; (void)n_in; (void)out_size;
    const float* pc = (const float*)d_in[0];
    float* out = (float*)d_out;

    // 128K pts + 16K tile boxes + 1K super boxes + 32K merge = 177 KB
    const int smem_bytes = NN * 16 + 2 * NTILE * 16 + 2 * NSUPER * 16 + 256 * KK * 8;
    cudaFuncSetAttribute(knn_global_kernel,
                         cudaFuncAttributeMaxDynamicSharedMemorySize,
                         smem_bytes);

    sort_kernel<<<BB, 512>>>(pc);
    dim3 g1(NN / 256, BB);
    knn_global_kernel<<<g1, 512, smem_bytes>>>(pc);
    knn_patch_kernel<<<BB * NPATCH, PP>>>(pc, out);
}

// round 14
// speedup vs baseline: 2.3748x; 2.3748x over previous
#include <cuda_runtime.h>
#include <math.h>

// Problem constants (fixed shapes per reference)
#define BB 4
#define NN 8192
#define KK 16
#define NPATCH 32
#define PP 256            // points per patch
#define NTILE 512         // 16-point tiles per batch
#define TSZ 16            // tile size
#define NCELL 4096        // 16^3 Morton cells
#define BCAP 32           // per-thread hit buffer capacity

// ---------------- scratch (no allocations allowed) ----------------
__device__ float4 g_sorted[BB * NN];       // spatially sorted points (+|c|^2 in .w)
__device__ int    g_perm[BB * NN];         // sorted slot -> original index
__device__ float  g_nrm_abs[BB * NN * 3];  // |global normal| (original index order)
__device__ float  g_sv[BB * NN];           // global surface variance
__device__ double g_pn[BB * NPATCH];       // per-patch partial normal loss
__device__ double g_psv[BB * NPATCH];      // per-patch partial surfvar loss
__device__ unsigned int g_done;            // patch-block arrival counter
__device__ int    g_hist[BB * NCELL];      // per-batch cell histogram (zeroed after use)
__device__ int    g_off[BB * NCELL];       // per-batch exclusive cell offsets
__device__ int    g_cnt[BB * NCELL];       // per-batch scatter counters (zeroed before use)

// ---------------- sorted insertion into ascending top-16 ----------------
__device__ __forceinline__ void insert16(float v, int j, float (&ds)[KK], int (&is)[KK]) {
    bool pt = v < ds[KK - 1];
#pragma unroll
    for (int t = KK - 1; t >= 1; --t) {
        bool pm = v < ds[t - 1];
        float nv = pm ? ds[t - 1] : v;
        int   ni = pm ? is[t - 1] : j;
        ds[t] = pt ? nv : ds[t];
        is[t] = pt ? ni : is[t];
        pt = pm;
    }
    ds[0] = pt ? v : ds[0];
    is[0] = pt ? j : is[0];
}

// ---------------- analytic 3x3 symmetric eigensolver ----------------
__device__ __forceinline__ void eig3(float a00, float a01, float a02,
                                     float a11, float a12, float a22,
                                     float &l0, float &l1, float &l2,
                                     float &vx, float &vy, float &vz) {
    float q = (a00 + a11 + a22) * (1.0f / 3.0f);
    float b00 = a00 - q, b11 = a11 - q, b22 = a22 - q;
    float p1 = a01 * a01 + a02 * a02 + a12 * a12;
    float p2 = b00 * b00 + b11 * b11 + b22 * b22 + 2.0f * p1;
    if (p2 <= 1e-30f) {
        l0 = l1 = l2 = q;
        vx = 1.0f; vy = 0.0f; vz = 0.0f;
        return;
    }
    float p = sqrtf(p2 * (1.0f / 6.0f));
    float ip = 1.0f / p;
    float c00 = b00 * ip, c11 = b11 * ip, c22 = b22 * ip;
    float c01 = a01 * ip, c02 = a02 * ip, c12 = a12 * ip;
    float det = c00 * (c11 * c22 - c12 * c12)
              - c01 * (c01 * c22 - c12 * c02)
              + c02 * (c01 * c12 - c11 * c02);
    float r = 0.5f * det;
    r = fminf(1.0f, fmaxf(-1.0f, r));
    float phi = acosf(r) * (1.0f / 3.0f);
    float two_p = 2.0f * p;
    l2 = q + two_p * cosf(phi);                          // largest
    l0 = q + two_p * cosf(phi + 2.0943951023931953f);    // smallest
    l1 = 3.0f * q - l2 - l0;

    float m00 = a00 - l0, m11 = a11 - l0, m22 = a22 - l0;
    float x0 = a01 * a12 - a02 * m11;
    float y0 = a02 * a01 - m00 * a12;
    float z0 = m00 * m11 - a01 * a01;
    float x1 = a01 * m22 - a02 * a12;
    float y1 = a02 * a02 - m00 * m22;
    float z1 = m00 * a12 - a01 * a02;
    float x2 = m11 * m22 - a12 * a12;
    float y2 = a12 * a02 - a01 * m22;
    float z2 = a01 * a12 - m11 * a02;
    float n0 = x0 * x0 + y0 * y0 + z0 * z0;
    float n1 = x1 * x1 + y1 * y1 + z1 * z1;
    float n2 = x2 * x2 + y2 * y2 + z2 * z2;
    float bx = x0, by = y0, bz = z0, bn = n0;
    if (n1 > bn) { bx = x1; by = y1; bz = z1; bn = n1; }
    if (n2 > bn) { bx = x2; by = y2; bz = z2; bn = n2; }
    if (bn < 1e-40f) { bx = 1.0f; by = 0.0f; bz = 0.0f; bn = 1.0f; }
    float inv = rsqrtf(bn);
    vx = bx * inv; vy = by * inv; vz = bz * inv;
}

// ---------------- covariance of centered neighbor set + eig ----------------
__device__ __forceinline__ void cov_eig(const float4* __restrict__ sh,
                                        float qx, float qy, float qz,
                                        const int (&is)[KK],
                                        float &l0, float &l1, float &l2,
                                        float &vx, float &vy, float &vz) {
    float a00 = 0.f, a01 = 0.f, a02 = 0.f, a11 = 0.f, a12 = 0.f, a22 = 0.f;
#pragma unroll
    for (int t = 0; t < KK; ++t) {
        float4 nb = sh[is[t]];
        float dx = nb.x - qx, dy = nb.y - qy, dz = nb.z - qz;
        a00 = fmaf(dx, dx, a00); a01 = fmaf(dx, dy, a01); a02 = fmaf(dx, dz, a02);
        a11 = fmaf(dy, dy, a11); a12 = fmaf(dy, dz, a12); a22 = fmaf(dz, dz, a22);
    }
    eig3(a00, a01, a02, a11, a12, a22, l0, l1, l2, vx, vy, vz);
}

// ---------------- Morton cell code (12-bit, 16^3 over [-4,4]) ----------------
__device__ __forceinline__ unsigned int morton12(float x, float y, float z) {
    int ux = min(15, max(0, (int)((x + 4.0f) * 2.0f)));
    int uy = min(15, max(0, (int)((y + 4.0f) * 2.0f)));
    int uz = min(15, max(0, (int)((z + 4.0f) * 2.0f)));
    unsigned int code = 0;
#pragma unroll
    for (int b = 0; b < 4; ++b) {
        code |= ((ux >> b) & 1) << (3 * b + 0);
        code |= ((uy >> b) & 1) << (3 * b + 1);
        code |= ((uz >> b) & 1) << (3 * b + 2);
    }
    return code;
}

// ---------------- kernel 0a: histogram (16 blocks) ----------------
// g_hist starts zero (device globals zero-init) and is re-zeroed by scan_kernel
// after use, so every graph replay sees a clean histogram.
__global__ void __launch_bounds__(512)
hist_kernel(const float* __restrict__ pc) {
    const int b     = blockIdx.x >> 2;        // batch
    const int chunk = blockIdx.x & 3;         // quarter of the batch
    const float* base = pc + (size_t)b * NN * 3;
    const int t = threadIdx.x;

    if (blockIdx.x == 0 && t == 0) g_done = 0;   // reset arrival counter

    const int i0 = chunk * (NN / 4);
    for (int i = i0 + t; i < i0 + NN / 4; i += 512) {
        float x = base[i * 3 + 0];
        float y = base[i * 3 + 1];
        float z = base[i * 3 + 2];
        atomicAdd(&g_hist[b * NCELL + morton12(x, y, z)], 1);
    }
}

// ---------------- kernel 0b: scan offsets + re-zero hist/cnt ----------------
__global__ void __launch_bounds__(512)
scan_kernel(const float* __restrict__ pc) {
    __shared__ int part[512];
    const int b = blockIdx.x;
    const int t = threadIdx.x;

    // load this batch's 4096-bin histogram (8 bins/thread)
    int h[8];
    int s = 0;
#pragma unroll
    for (int u = 0; u < 8; ++u) { h[u] = g_hist[b * NCELL + t * 8 + u]; s += h[u]; }
    part[t] = s;
    __syncthreads();
    for (int o = 1; o < 512; o <<= 1) {
        int v = (t >= o) ? part[t - o] : 0;
        __syncthreads();
        part[t] += v;
        __syncthreads();
    }
    int basev = part[t] - s;
#pragma unroll
    for (int u = 0; u < 8; ++u) {
        g_off[b * NCELL + t * 8 + u] = basev;
        basev += h[u];
        g_hist[b * NCELL + t * 8 + u] = 0;   // re-zero for next replay
        g_cnt[b * NCELL + t * 8 + u] = 0;    // zero scatter counters
    }
}

// ---------------- kernel 0c: scatter (16 blocks) ----------------
__global__ void __launch_bounds__(512)
scatter_kernel(const float* __restrict__ pc) {
    const int b     = blockIdx.x >> 2;
    const int chunk = blockIdx.x & 3;
    const float* base = pc + (size_t)b * NN * 3;
    const int t = threadIdx.x;

    const int i0 = chunk * (NN / 4);
    for (int i = i0 + t; i < i0 + NN / 4; i += 512) {
        float x = base[i * 3 + 0];
        float y = base[i * 3 + 1];
        float z = base[i * 3 + 2];
        unsigned int c = morton12(x, y, z);
        int pos = g_off[b * NCELL + c] + atomicAdd(&g_cnt[b * NCELL + c], 1);
        float c2 = __fadd_rn(__fadd_rn(__fmul_rn(x, x), __fmul_rn(y, y)), __fmul_rn(z, z));
        g_sorted[b * NN + pos] = make_float4(x, y, z, c2);
        g_perm[b * NN + pos] = i;
    }
}

// ---------------- kernel 1: global kNN, outward tile scan + seeded wmax ------
// (identical to the 205us round-11 kernel)
// smem layout: float4 pts[8192] | float4 boxmin[512] | float4 boxmax[512]
//              | float mds[256*16] | int mis[256*16]   (176 KB)
extern __shared__ unsigned char smem_raw[];

__global__ void __launch_bounds__(512, 1)
knn_global_kernel(const float* __restrict__ pc) {
    float4* sh     = (float4*)smem_raw;
    float4* boxmin = (float4*)(smem_raw + NN * 16);
    float4* boxmax = (float4*)(smem_raw + NN * 16 + NTILE * 16);
    float*  mds    = (float*)(smem_raw + NN * 16 + 2 * NTILE * 16);
    int*    mis    = (int*)(smem_raw + NN * 16 + 2 * NTILE * 16 + 256 * KK * 4);

    const int b = blockIdx.y;
    const float4* gs = g_sorted + b * NN;

    // stage sorted points
    for (int i = threadIdx.x; i < NN; i += 512) sh[i] = gs[i];
    __syncthreads();

    // tile AABBs (512 tiles, one per thread)
    {
        const int T = threadIdx.x;
        float4 p0 = sh[T * TSZ];
        float mnx = p0.x, mny = p0.y, mnz = p0.z;
        float mxx = p0.x, mxy = p0.y, mxz = p0.z;
#pragma unroll
        for (int u = 1; u < TSZ; ++u) {
            float4 p = sh[T * TSZ + u];
            mnx = fminf(mnx, p.x); mny = fminf(mny, p.y); mnz = fminf(mnz, p.z);
            mxx = fmaxf(mxx, p.x); mxy = fmaxf(mxy, p.y); mxz = fmaxf(mxz, p.z);
        }
        boxmin[T] = make_float4(mnx, mny, mnz, 0.f);
        boxmax[T] = make_float4(mxx, mxy, mxz, 0.f);
    }
    __syncthreads();

    const int q    = threadIdx.x & 255;       // query slot within block
    const int half = threadIdx.x >> 8;        // tile-parity this thread scans
    const int qi   = blockIdx.x * 256 + q;    // sorted index of query

    float4 qp = sh[qi];
    const float qx = qp.x, qy = qp.y, qz = qp.z, q2 = qp.w;
    const float nqx = -2.0f * qx, nqy = -2.0f * qy, nqz = -2.0f * qz;

    // --- seed: own tile has exactly 16 points -> max of their computed rank
    //     keys is a valid upper bound on the final 16th key. Ladder-free.
    float wmax = -3.4e38f;
    {
        const int jb0 = (qi >> 4) << 4;
#pragma unroll
        for (int u = 0; u < TSZ; ++u) {
            float4 c = sh[jb0 + u];
            float d = fmaf(c.x, nqx, fmaf(c.y, nqy, fmaf(c.z, nqz, c.w)));
            wmax = fmaxf(wmax, d);
        }
    }
    // prune threshold in true-d2 space, inflated for rank-key rounding slack
    float wmax_d2 = fmaf(fabsf(wmax + q2), 1e-4f, wmax + q2) + 1e-6f;

    float ds[KK];
    int   is[KK];
#pragma unroll
    for (int t = 0; t < KK; ++t) { ds[t] = 3.4e38f; is[t] = 0; }

    float bufd[BCAP];
    int   bufi[BCAP];
    int   cnt = 0;

    // warp-uniform outward tile order, restricted to this thread's parity
    const int own_tile = qi >> 4;
    int tb = __shfl_sync(0xffffffffu, own_tile, 16);
    int start = (tb & ~1) | half;
    int a = start, bd = start - 2;

    for (int s = 0; s < NTILE / 2; ++s) {
        int T;
        bool canA = (a < NTILE), canB = (bd >= 0);
        if (canA && (!canB || ((s & 1) == 0))) { T = a; a += 2; }
        else                                   { T = bd; bd -= 2; }

        // conservative AABB lower bound on d2 for every point in tile T
        float4 bmn = boxmin[T];
        float4 bmx = boxmax[T];
        float dx = fmaxf(fmaxf(bmn.x - qx, qx - bmx.x), 0.f);
        float dy = fmaxf(fmaxf(bmn.y - qy, qy - bmx.y), 0.f);
        float dz = fmaxf(fmaxf(bmn.z - qz, qz - bmx.z), 0.f);
        float d2b = fmaf(dx, dx, fmaf(dy, dy, dz * dz));
        bool hit = d2b < wmax_d2;

        if (__any_sync(0xffffffffu, hit)) {
            const int jb = T << 4;
#pragma unroll
            for (int u = 0; u < TSZ; ++u) {
                float4 c = sh[jb + u];
                float d = fmaf(c.x, nqx, fmaf(c.y, nqy, fmaf(c.z, nqz, c.w)));
                if (d <= wmax) {            // <= keeps the seed-boundary point
                    bufd[cnt] = d;
                    bufi[cnt] = jb + u;
                    ++cnt;
                }
            }
            if (__any_sync(0xffffffffu, cnt > BCAP - TSZ)) {
#pragma unroll
                for (int t = 0; t < BCAP; ++t) {
                    if (t < cnt) insert16(bufd[t], bufi[t], ds, is);
                }
                cnt = 0;
                wmax = fminf(wmax, ds[KK - 1]);
                wmax_d2 = fmaf(fabsf(wmax + q2), 1e-4f, wmax + q2) + 1e-6f;
            }
        }
    }
    // drain remaining buffered hits
#pragma unroll
    for (int t = 0; t < BCAP; ++t) {
        if (t < cnt) insert16(bufd[t], bufi[t], ds, is);
    }

    // merge the two parity halves
    if (half) {
#pragma unroll
        for (int t = 0; t < KK; ++t) {
            mds[q * KK + t] = ds[t];
            mis[q * KK + t] = is[t];
        }
    }
    __syncthreads();

    if (!half) {
#pragma unroll
        for (int t = 0; t < KK; ++t) {
            float v = mds[q * KK + t];
            if (v < ds[KK - 1]) insert16(v, mis[q * KK + t], ds, is);
        }

        float l0, l1, l2, vx, vy, vz;
        cov_eig(sh, qx, qy, qz, is, l0, l1, l2, vx, vy, vz);

        const int gi = b * NN + g_perm[b * NN + qi];   // original point index
        g_nrm_abs[gi * 3 + 0] = fabsf(vx);
        g_nrm_abs[gi * 3 + 1] = fabsf(vy);
        g_nrm_abs[gi * 3 + 2] = fabsf(vz);
        g_sv[gi] = l0 / (l0 + l1 + l2);
    }
}

// ---------------- kernel 2: patch kNN + eig + loss + folded final reduction ---
__global__ void __launch_bounds__(PP, 4)
knn_patch_kernel(const float* __restrict__ pc, float* __restrict__ out) {
    __shared__ float4 shp[PP];
    __shared__ double s_n[PP];
    __shared__ double s_sv[PP];
    __shared__ bool   s_last;

    const int patch = blockIdx.x;              // 0 .. BB*NPATCH-1
    const float* base = pc + (size_t)patch * PP * 3;
    const int t = threadIdx.x;

    {
        float x = base[t * 3 + 0];
        float y = base[t * 3 + 1];
        float z = base[t * 3 + 2];
        float c2 = __fadd_rn(__fadd_rn(__fmul_rn(x, x), __fmul_rn(y, y)), __fmul_rn(z, z));
        shp[t] = make_float4(x, y, z, c2);
    }
    __syncthreads();

    float4 qp = shp[t];
    const float nqx = -2.0f * qp.x, nqy = -2.0f * qp.y, nqz = -2.0f * qp.z;

    float ds[KK];
    int   is[KK];
#pragma unroll
    for (int k = 0; k < KK; ++k) { ds[k] = 3.4e38f; is[k] = 0; }

    {
        float bufd[BCAP];
        int   bufi[BCAP];
        int   cnt = 0;
        float wmax = 3.4e38f;
        for (int j = 0; j < PP; j += 8) {
            float d[8];
#pragma unroll
            for (int u = 0; u < 8; ++u) {
                float4 c = shp[j + u];
                d[u] = fmaf(c.x, nqx, fmaf(c.y, nqy, fmaf(c.z, nqz, c.w)));
            }
            float m = fminf(fminf(fminf(d[0], d[1]), fminf(d[2], d[3])),
                            fminf(fminf(d[4], d[5]), fminf(d[6], d[7])));
            if (m < wmax) {
#pragma unroll
                for (int u = 0; u < 8; ++u) {
                    if (d[u] < wmax) { bufd[cnt] = d[u]; bufi[cnt] = j + u; ++cnt; }
                }
            }
            if (__any_sync(0xffffffffu, cnt > BCAP - 8)) {
#pragma unroll
                for (int s = 0; s < BCAP; ++s) {
                    if (s < cnt) insert16(bufd[s], bufi[s], ds, is);
                }
                cnt = 0;
                wmax = ds[KK - 1];
            }
        }
#pragma unroll
        for (int s = 0; s < BCAP; ++s) {
            if (s < cnt) insert16(bufd[s], bufi[s], ds, is);
        }
    }

    float l0, l1, l2, vx, vy, vz;
    cov_eig(shp, qp.x, qp.y, qp.z, is, l0, l1, l2, vx, vy, vz);

    const int gi = patch * PP + t;   // == flat [B, N] original index
    float svp = l0 / (l0 + l1 + l2);

    float gx = g_nrm_abs[gi * 3 + 0];
    float gy = g_nrm_abs[gi * 3 + 1];
    float gz = g_nrm_abs[gi * 3 + 2];
    float ex = fabsf(vx) - gx;
    float ey = fabsf(vy) - gy;
    float ez = fabsf(vz) - gz;
    float ln = sqrtf(ex * ex + ey * ey + ez * ez);

    float dsv = svp - g_sv[gi];
    float lsv = dsv * dsv;

    // deterministic block reduction
    s_n[t]  = (double)ln;
    s_sv[t] = (double)lsv;
    __syncthreads();
#pragma unroll
    for (int s = PP / 2; s > 0; s >>= 1) {
        if (t < s) { s_n[t] += s_n[t + s]; s_sv[t] += s_sv[t + s]; }
        __syncthreads();
    }
    if (t == 0) {
        g_pn[patch]  = s_n[0];
        g_psv[patch] = s_sv[0];
        __threadfence();
        unsigned int v = atomicAdd(&g_done, 1);
        s_last = (v == BB * NPATCH - 1);
    }
    __syncthreads();

    // last-arriving block performs the deterministic final reduction
    if (s_last) {
        if (t < BB * NPATCH) {
            s_n[t]  = __ldcg(&g_pn[t]);     // bypass L1: other SMs wrote these
            s_sv[t] = __ldcg(&g_psv[t]);
        } else {
            s_n[t] = 0.0; s_sv[t] = 0.0;
        }
        __syncthreads();
#pragma unroll
        for (int s = PP / 2; s > 0; s >>= 1) {
            if (t < s) { s_n[t] += s_n[t + s]; s_sv[t] += s_sv[t + s]; }
            __syncthreads();
        }
        if (t == 0) {
            const double inv = 1.0 / (double)(BB * NN);
            out[0] = (float)(s_n[0]  * inv);   // * W_NORMAL (=1)
            out[1] = (float)(s_sv[0] * inv);   // * W_SURFVAR (=1)
        }
    }
}

// ---------------- launcher ----------------
extern "C" void kernel_launch(void* const* d_in, const int* in_sizes, int n_in,
                              void* d_out, int out_size) {
    (void)in_sizes; (void)n_in; (void)out_size;
    const float* pc = (const float*)d_in[0];
    float* out = (float*)d_out;

    const int smem_bytes = NN * 16 + 2 * NTILE * 16 + 256 * KK * 8;  // 176 KB
    cudaFuncSetAttribute(knn_global_kernel,
                         cudaFuncAttributeMaxDynamicSharedMemorySize,
                         smem_bytes);

    hist_kernel<<<BB * 4, 512>>>(pc);
    scan_kernel<<<BB, 512>>>(pc);
    scatter_kernel<<<BB * 4, 512>>>(pc);
    dim3 g1(NN / 256, BB);
    knn_global_kernel<<<g1, 512, smem_bytes>>>(pc);
    knn_patch_kernel<<<BB * NPATCH, PP>>>(pc, out);
}